// round 1
// baseline (speedup 1.0000x reference)
#include <cuda_runtime.h>
#include <cuda_bf16.h>
#include <cstdint>

// Problem constants (AutoregressivePrior: HID=256, K=7, batch=32768, zm=64)
#define HID   256
#define KSTEP 7
#define ZM    64

#define CL  8      // cluster size (CTAs)
#define TPB 256    // threads per CTA

// scratch for the [2][7][64] loc/scale table
__device__ float g_scratch[2 * KSTEP * ZM];

__device__ __forceinline__ uint32_t smem_u32(const void* p) {
    return (uint32_t)__cvta_generic_to_shared(p);
}

__device__ __forceinline__ void cluster_sync_() {
    asm volatile("barrier.cluster.arrive.aligned;" ::: "memory");
    asm volatile("barrier.cluster.wait.aligned;" ::: "memory");
}

__device__ __forceinline__ void st_cluster_f32(uint32_t laddr, int rank, float v) {
    uint32_t ra;
    asm volatile("mapa.shared::cluster.u32 %0, %1, %2;" : "=r"(ra) : "r"(laddr), "r"(rank));
    asm volatile("st.shared::cluster.f32 [%0], %1;" :: "r"(ra), "f"(v) : "memory");
}

__device__ __forceinline__ float sigf(float x) {
    return 1.0f / (1.0f + __expf(-x));
}

// ---------------------------------------------------------------------------
// Kernel 1: 8-CTA cluster computes the 6 LSTM steps + loc/scale projections.
// 2 threads per gate output (1024 outputs total across the cluster).
// W_sum = W_ih + W_hh held register-resident (steps 2..6 use x == h).
// Step 1 (h=0) is computed during the weight-load pass with x = zm_1.
// ---------------------------------------------------------------------------
__global__ void __cluster_dims__(CL, 1, 1) __launch_bounds__(TPB, 1)
lstm_prior_kernel(const float* __restrict__ zm1,
                  const float* __restrict__ W_ih,  const float* __restrict__ W_hh,
                  const float* __restrict__ b_ih,  const float* __restrict__ b_hh,
                  const float* __restrict__ W_loc, const float* __restrict__ b_loc,
                  const float* __restrict__ W_scale, const float* __restrict__ b_scale)
{
    __shared__ __align__(16) float zm_sh[HID];
    __shared__ __align__(16) float h_sh[HID];
    __shared__ __align__(16) float gbuf[2][4 * HID];   // double-buffered gate exchange
    __shared__ __align__(16) float pz[KSTEP * HID];    // replicated p_z rows

    const int t    = threadIdx.x;
    const int r    = blockIdx.x;       // cluster rank (grid == one cluster of 8)
    const int half = t & 1;            // which half of the 256-dot this thread owns
    const int o    = r * 128 + (t >> 1);  // global gate index [0,1024)

    // row 0 of p_z is zm_1; also stage zm_1 for the step-1 matvec
    {
        float z = zm1[t];
        zm_sh[t] = z;
        pz[t]    = z;
    }
    __syncthreads();

    const float b_reg = b_ih[o] + b_hh[o];

    // ---- load W_ih/W_hh slices, build register W_sum, fuse step-1 matvec ----
    float4 wsum[32];
    float gate1;
    {
        const float4* Wi  = (const float4*)W_ih;
        const float4* Wh  = (const float4*)W_hh;
        const float4* zm4 = (const float4*)zm_sh;
        const int wbase = o * (HID / 4) + half * 32;
        float a0 = 0.f, a1 = 0.f;
        #pragma unroll
        for (int i = 0; i < 32; i++) {
            float4 wi = Wi[wbase + i];
            float4 wh = Wh[wbase + i];
            float4 z  = zm4[half * 32 + i];
            a0 = fmaf(wi.x, z.x, a0); a1 = fmaf(wi.y, z.y, a1);
            a0 = fmaf(wi.z, z.z, a0); a1 = fmaf(wi.w, z.w, a1);
            wsum[i] = make_float4(wi.x + wh.x, wi.y + wh.y, wi.z + wh.z, wi.w + wh.w);
        }
        float s = a0 + a1;
        s += __shfl_xor_sync(0xffffffffu, s, 1);
        gate1 = s + b_reg;
    }

    // ---- 6 LSTM steps ----
    float c_reg = 0.f;   // thread t owns c[j], j = t
    for (int s = 1; s <= KSTEP - 1; s++) {
        float gate;
        if (s == 1) {
            gate = gate1;
        } else {
            const float4* h4 = (const float4*)h_sh;
            float a0 = 0.f, a1 = 0.f;
            #pragma unroll
            for (int i = 0; i < 32; i++) {
                float4 w = wsum[i];
                float4 h = h4[half * 32 + i];
                a0 = fmaf(w.x, h.x, a0); a1 = fmaf(w.y, h.y, a1);
                a0 = fmaf(w.z, h.z, a0); a1 = fmaf(w.w, h.w, a1);
            }
            float ss = a0 + a1;
            ss += __shfl_xor_sync(0xffffffffu, ss, 1);
            gate = ss + b_reg;
        }

        // broadcast this CTA's 128 gates to all 8 CTAs (double-buffered)
        float* gb = gbuf[s & 1];
        if (half == 0) {
            uint32_t laddr = smem_u32(&gb[o]);
            #pragma unroll
            for (int d = 0; d < CL; d++)
                st_cluster_f32(laddr, d, gate);
        }
        cluster_sync_();

        // each CTA now has all 1024 gates locally; compute h/c (replicated)
        const int j = t;
        float gi = gb[j];
        float gf = gb[HID + j];
        float gg = gb[2 * HID + j];
        float go = gb[3 * HID + j];
        c_reg = sigf(gf) * c_reg + sigf(gi) * tanhf(gg);
        float h = sigf(go) * tanhf(c_reg);
        h_sh[j] = h;
        pz[s * HID + j] = h;
        __syncthreads();
    }

    // ---- projections: 896 outputs = 2 tensors x 7 rows x 64 cols, 112 per CTA ----
    if (t < 112) {
        int u    = r * 112 + t;                 // [0, 896)
        int tsel = (u >= KSTEP * ZM);           // 0 = loc, 1 = scale
        int rem  = u - tsel * (KSTEP * ZM);
        int kk   = rem >> 6;                    // p_z row
        int col  = rem & 63;                    // output column
        const float4* W = (const float4*)(tsel ? W_scale : W_loc);
        const float*  b = tsel ? b_scale : b_loc;
        const float4* x = (const float4*)&pz[kk * HID];
        float a0 = 0.f, a1 = 0.f, a2 = 0.f, a3 = 0.f;
        #pragma unroll
        for (int i = 0; i < HID / 4; i++) {
            float4 w = W[col * (HID / 4) + i];
            float4 v = x[i];
            a0 = fmaf(w.x, v.x, a0); a1 = fmaf(w.y, v.y, a1);
            a2 = fmaf(w.z, v.z, a2); a3 = fmaf(w.w, v.w, a3);
        }
        g_scratch[u] = (a0 + a1) + (a2 + a3) + b[col];
    }
}

// ---------------------------------------------------------------------------
// Kernel 2: broadcast the [14][64] table to [2*K*batch, 64]. Pure HBM writes.
// Each output float4: seg = idx4 >> 19 (32768 rows * 16 float4/row per segment),
// col4 = idx4 & 15.
// ---------------------------------------------------------------------------
__global__ void __launch_bounds__(256)
broadcast_kernel(float4* __restrict__ out, int total4)
{
    __shared__ float4 tab[2 * KSTEP * ZM / 4];   // 224 float4 = 3.5 KB
    if (threadIdx.x < 2 * KSTEP * ZM / 4)
        tab[threadIdx.x] = ((const float4*)g_scratch)[threadIdx.x];
    __syncthreads();

    int stride = gridDim.x * blockDim.x;
    for (int idx = blockIdx.x * blockDim.x + threadIdx.x; idx < total4; idx += stride) {
        int col4 = idx & 15;
        int seg  = idx >> 19;          // batch(32768) * 16 float4 per (tensor,k) segment
        out[idx] = tab[seg * 16 + col4];
    }
}

extern "C" void kernel_launch(void* const* d_in, const int* in_sizes, int n_in,
                              void* d_out, int out_size)
{
    const float* zm1     = (const float*)d_in[0];
    const float* W_ih    = (const float*)d_in[1];
    const float* W_hh    = (const float*)d_in[2];
    const float* b_ih    = (const float*)d_in[3];
    const float* b_hh    = (const float*)d_in[4];
    const float* W_loc   = (const float*)d_in[5];
    const float* b_loc   = (const float*)d_in[6];
    const float* W_scale = (const float*)d_in[7];
    const float* b_scale = (const float*)d_in[8];

    lstm_prior_kernel<<<CL, TPB>>>(zm1, W_ih, W_hh, b_ih, b_hh,
                                   W_loc, b_loc, W_scale, b_scale);

    int total4 = out_size / 4;                 // 7,340,032 float4
    broadcast_kernel<<<1184, 256>>>((float4*)d_out, total4);
}

// round 2
// speedup vs baseline: 1.1607x; 1.1607x over previous
#include <cuda_runtime.h>
#include <cuda_bf16.h>
#include <cstdint>

// Problem constants (AutoregressivePrior: HID=256, K=7, batch=32768, zm=64)
#define HID   256
#define KSTEP 7
#define ZM    64

#define CL  8      // cluster size (CTAs)
#define TPB 256    // threads per CTA

// [2][7][64] loc/scale table
__device__ __align__(16) float g_scratch[2 * KSTEP * ZM];

// Dynamic SMEM layout (floats):
//   wst   : 128 rows * 260 (pitch, 65 float4)  = 33280
//   zm_sh : 256
//   h_sh  : 256
//   gbuf  : 2 * 1024
//   pz    : 7 * 256
#define WST_F   (128 * 260)
#define SMEM_F  (WST_F + 256 + 256 + 2048 + KSTEP * HID)
#define SMEM_BYTES (SMEM_F * 4)

__device__ __forceinline__ uint32_t smem_u32(const void* p) {
    return (uint32_t)__cvta_generic_to_shared(p);
}
__device__ __forceinline__ void cluster_sync_() {
    asm volatile("barrier.cluster.arrive.aligned;" ::: "memory");
    asm volatile("barrier.cluster.wait.aligned;" ::: "memory");
}
__device__ __forceinline__ void st_cluster_f32(uint32_t laddr, int rank, float v) {
    uint32_t ra;
    asm volatile("mapa.shared::cluster.u32 %0, %1, %2;" : "=r"(ra) : "r"(laddr), "r"(rank));
    asm volatile("st.shared::cluster.f32 [%0], %1;" :: "r"(ra), "f"(v) : "memory");
}
__device__ __forceinline__ float sigf(float x) {
    return 1.0f / (1.0f + __expf(-x));
}

// ---------------------------------------------------------------------------
// Kernel 1: 8-CTA cluster. 2 threads per gate output (1024 gates).
// Weights staged COALESCED through padded SMEM, then held register-resident.
// Steps 2..6 use x == h  =>  W_sum = W_ih + W_hh. Step 1 (h=0) fused into
// the W_ih staging pass with x = zm_1.
// ---------------------------------------------------------------------------
__global__ void __cluster_dims__(CL, 1, 1) __launch_bounds__(TPB, 1)
lstm_prior_kernel(const float* __restrict__ zm1,
                  const float* __restrict__ W_ih,  const float* __restrict__ W_hh,
                  const float* __restrict__ b_ih,  const float* __restrict__ b_hh,
                  const float* __restrict__ W_loc, const float* __restrict__ b_loc,
                  const float* __restrict__ W_scale, const float* __restrict__ b_scale)
{
    extern __shared__ __align__(16) float sm[];
    float4* wst4  = (float4*)sm;                    // [128][65] float4 (pitched)
    float*  zm_sh = sm + WST_F;
    float*  h_sh  = zm_sh + 256;
    float*  gbuf_ = h_sh + 256;                     // [2][1024]
    float*  pz    = gbuf_ + 2048;                   // [7][256]

    const int t    = threadIdx.x;
    const int r    = blockIdx.x;          // cluster rank
    const int half = t & 1;
    const int ol   = t >> 1;              // local gate row [0,128)
    const int o    = r * 128 + ol;        // global gate index [0,1024)

    {   // p_z row 0 = zm_1; also stage zm_1 for the fused step-1 matvec
        float z = zm1[t];
        zm_sh[t] = z;
        pz[t]    = z;
    }

    const float b_reg = b_ih[o] + b_hh[o];

    // ---- Pass A: coalesced stage of this CTA's W_ih slice (128KB) ----
    {
        const float4* Wi = (const float4*)W_ih + (size_t)r * 128 * 64;
        #pragma unroll
        for (int k = 0; k < 32; k++) {
            int idx = t + k * 256;
            wst4[(idx >> 6) * 65 + (idx & 63)] = Wi[idx];
        }
    }
    __syncthreads();

    // read my register slice + fused step-1 dot (h=0 => gates = W_ih @ zm + b)
    float4 wsum[32];
    float gate1;
    {
        const float4* myrow = wst4 + ol * 65 + half * 32;
        const float4* zm4   = (const float4*)zm_sh;
        float a0 = 0.f, a1 = 0.f;
        #pragma unroll
        for (int i = 0; i < 32; i++) {
            float4 w = myrow[i];
            float4 z = zm4[half * 32 + i];
            wsum[i] = w;
            a0 = fmaf(w.x, z.x, a0); a1 = fmaf(w.y, z.y, a1);
            a0 = fmaf(w.z, z.z, a0); a1 = fmaf(w.w, z.w, a1);
        }
        float s = a0 + a1;
        s += __shfl_xor_sync(0xffffffffu, s, 1);
        gate1 = s + b_reg;
    }
    __syncthreads();

    // ---- Pass B: coalesced stage of W_hh slice, accumulate into wsum ----
    {
        const float4* Wh = (const float4*)W_hh + (size_t)r * 128 * 64;
        #pragma unroll
        for (int k = 0; k < 32; k++) {
            int idx = t + k * 256;
            wst4[(idx >> 6) * 65 + (idx & 63)] = Wh[idx];
        }
    }
    __syncthreads();
    {
        const float4* myrow = wst4 + ol * 65 + half * 32;
        #pragma unroll
        for (int i = 0; i < 32; i++) {
            float4 w = myrow[i];
            wsum[i].x += w.x; wsum[i].y += w.y;
            wsum[i].z += w.z; wsum[i].w += w.w;
        }
    }

    // ---- 6 LSTM steps ----
    float c_reg = 0.f;                     // thread t owns c[t]
    for (int s = 1; s <= KSTEP - 1; s++) {
        float gate;
        if (s == 1) {
            gate = gate1;
        } else {
            const float4* h4 = (const float4*)h_sh;
            float a0 = 0.f, a1 = 0.f;
            #pragma unroll
            for (int i = 0; i < 32; i++) {
                float4 w = wsum[i];
                float4 h = h4[half * 32 + i];
                a0 = fmaf(w.x, h.x, a0); a1 = fmaf(w.y, h.y, a1);
                a0 = fmaf(w.z, h.z, a0); a1 = fmaf(w.w, h.w, a1);
            }
            float ss = a0 + a1;
            ss += __shfl_xor_sync(0xffffffffu, ss, 1);
            gate = ss + b_reg;
        }

        // broadcast this CTA's 128 gates to all 8 CTAs (double-buffered)
        float* gb = gbuf_ + (s & 1) * 1024;
        if (half == 0) {
            uint32_t laddr = smem_u32(&gb[o]);
            #pragma unroll
            for (int d = 0; d < CL; d++)
                st_cluster_f32(laddr, d, gate);
        }
        cluster_sync_();

        // every CTA now has all 1024 gates locally; replicated h/c update
        const int j = t;
        float gi = gb[j];
        float gf = gb[HID + j];
        float gg = gb[2 * HID + j];
        float go = gb[3 * HID + j];
        c_reg = sigf(gf) * c_reg + sigf(gi) * tanhf(gg);
        float h = sigf(go) * tanhf(c_reg);
        h_sh[j] = h;
        pz[s * HID + j] = h;
        __syncthreads();
    }

    // ---- projections: warp-per-output, coalesced W row loads ----
    // 896 outputs / 64 warps = 14 per warp
    {
        const int wid  = t >> 5;
        const int lane = t & 31;
        const int gw   = r * 8 + wid;                // global warp id [0,64)
        const float4* pz4 = (const float4*)pz;
        #pragma unroll
        for (int m = 0; m < 14; m++) {
            int u    = gw * 14 + m;                  // [0,896)
            int tsel = (u >= KSTEP * ZM);
            int rem  = u - tsel * (KSTEP * ZM);
            int kk   = rem >> 6;
            int col  = rem & 63;
            const float4* Wr = (const float4*)(tsel ? W_scale : W_loc) + col * 64;
            float4 w0 = Wr[lane];
            float4 w1 = Wr[32 + lane];
            float4 x0 = pz4[kk * 64 + lane];
            float4 x1 = pz4[kk * 64 + 32 + lane];
            float a0 = 0.f, a1 = 0.f;
            a0 = fmaf(w0.x, x0.x, a0); a1 = fmaf(w0.y, x0.y, a1);
            a0 = fmaf(w0.z, x0.z, a0); a1 = fmaf(w0.w, x0.w, a1);
            a0 = fmaf(w1.x, x1.x, a0); a1 = fmaf(w1.y, x1.y, a1);
            a0 = fmaf(w1.z, x1.z, a0); a1 = fmaf(w1.w, x1.w, a1);
            float a = a0 + a1;
            #pragma unroll
            for (int d = 16; d > 0; d >>= 1)
                a += __shfl_xor_sync(0xffffffffu, a, d);
            if (lane == 0)
                g_scratch[u] = a + (tsel ? b_scale[col] : b_loc[col]);
        }
    }
}

// ---------------------------------------------------------------------------
// Kernel 2: broadcast [14][64] table to 117MB. Each CTA owns a fixed
// (segment, chunk); the table value is one register; inner loop is 16 pure
// fully-unrolled STG.128.
// grid = 14 segments * 128 CTAs; each CTA writes 4096 float4.
// ---------------------------------------------------------------------------
__global__ void __launch_bounds__(256)
broadcast_kernel(float4* __restrict__ out)
{
    const int seg = blockIdx.x >> 7;     // [0,14)
    const int sub = blockIdx.x & 127;
    const float4 v = ((const float4*)g_scratch)[seg * 16 + (threadIdx.x & 15)];
    float4* base = out + ((size_t)seg << 19) + (sub << 12) + threadIdx.x;
    #pragma unroll
    for (int i = 0; i < 16; i++)
        base[i * 256] = v;
}

extern "C" void kernel_launch(void* const* d_in, const int* in_sizes, int n_in,
                              void* d_out, int out_size)
{
    const float* zm1     = (const float*)d_in[0];
    const float* W_ih    = (const float*)d_in[1];
    const float* W_hh    = (const float*)d_in[2];
    const float* b_ih    = (const float*)d_in[3];
    const float* b_hh    = (const float*)d_in[4];
    const float* W_loc   = (const float*)d_in[5];
    const float* b_loc   = (const float*)d_in[6];
    const float* W_scale = (const float*)d_in[7];
    const float* b_scale = (const float*)d_in[8];

    static bool attr_set = false;
    if (!attr_set) {
        cudaFuncSetAttribute(lstm_prior_kernel,
                             cudaFuncAttributeMaxDynamicSharedMemorySize, SMEM_BYTES);
        attr_set = true;
    }

    lstm_prior_kernel<<<CL, TPB, SMEM_BYTES>>>(zm1, W_ih, W_hh, b_ih, b_hh,
                                               W_loc, b_loc, W_scale, b_scale);

    broadcast_kernel<<<14 * 128, 256>>>((float4*)d_out);
}

// round 3
// speedup vs baseline: 1.3938x; 1.2008x over previous
#include <cuda_runtime.h>
#include <cuda_bf16.h>
#include <cstdint>

// AutoregressivePrior: HID=256, K=7, batch=32768, zm=64
#define HID   256
#define KSTEP 7
#define ZM    64

#define CL    8        // LSTM cluster size (CTAs 0..7)
#define TPB   256
#define NBC   136      // broadcast CTAs (8..143)
#define GRID  144      // 18 clusters of 8, all resident in one wave
#define NITEM 224      // 14 segments * 16 sub-chunks, 512KB each

// [2][7][64] loc/scale table + sync objects
__device__ __align__(16) float g_scratch[2 * KSTEP * ZM];
__device__ int g_flag[KSTEP * 8];        // 32B-padded flags
__device__ unsigned g_cnt[KSTEP * 8];    // 32B-padded counters

// Dynamic SMEM layout (floats)
#define WST_F   (128 * 260)              // weight staging, pitched [128][65] float4
#define ZM_OFF  (WST_F)                  // 256
#define H_OFF   (ZM_OFF + 256)           // 256
#define GB_OFF  (H_OFF + 256)            // 2*1024
#define PZ_OFF  (GB_OFF + 2048)          // 7*256
#define PW_OFF  (PZ_OFF + KSTEP * HID)   // 16*260 proj weight rows (pitched)
#define PB_OFF  (PW_OFF + 16 * 260)      // 16 proj biases
#define SMEM_F  (PB_OFF + 16)
#define SMEM_BYTES (SMEM_F * 4)

__device__ __forceinline__ uint32_t smem_u32(const void* p) {
    return (uint32_t)__cvta_generic_to_shared(p);
}
__device__ __forceinline__ void cluster_sync_() {
    asm volatile("barrier.cluster.arrive.aligned;" ::: "memory");
    asm volatile("barrier.cluster.wait.aligned;" ::: "memory");
}
__device__ __forceinline__ void st_cluster_f32(uint32_t laddr, int rank, float v) {
    uint32_t ra;
    asm volatile("mapa.shared::cluster.u32 %0, %1, %2;" : "=r"(ra) : "r"(laddr), "r"(rank));
    asm volatile("st.shared::cluster.f32 [%0], %1;" :: "r"(ra), "f"(v) : "memory");
}
__device__ __forceinline__ int ld_acq(const int* p) {
    int v;
    asm volatile("ld.global.acquire.gpu.b32 %0, [%1];" : "=r"(v) : "l"(p) : "memory");
    return v;
}
__device__ __forceinline__ void st_rel(int* p, int v) {
    asm volatile("st.global.release.gpu.b32 [%0], %1;" :: "l"(p), "r"(v) : "memory");
}
__device__ __forceinline__ float sigf(float x) {
    return 1.0f / (1.0f + __expf(-x));
}

// ---------------------------------------------------------------------------
// warp-per-output projections for p_z row k; CTA r owns outputs [r*16, r*16+16)
// ---------------------------------------------------------------------------
__device__ __forceinline__ void proj_row(int k, int r, int t,
                                         const float* pw, const float* pb,
                                         const float* pz)
{
    const int w    = t >> 5;
    const int lane = t & 31;
    const float4* pw4 = (const float4*)pw;   // pitched [16][65]
    const float4* pz4 = (const float4*)pz;
    #pragma unroll
    for (int rep = 0; rep < 2; rep++) {
        int i = 2 * w + rep;                  // local output [0,16)
        float4 wa = pw4[i * 65 + lane];
        float4 wb = pw4[i * 65 + 32 + lane];
        float4 xa = pz4[k * 64 + lane];
        float4 xb = pz4[k * 64 + 32 + lane];
        float a0 = 0.f, a1 = 0.f, a2 = 0.f, a3 = 0.f;
        a0 = fmaf(wa.x, xa.x, a0); a1 = fmaf(wa.y, xa.y, a1);
        a2 = fmaf(wa.z, xa.z, a2); a3 = fmaf(wa.w, xa.w, a3);
        a0 = fmaf(wb.x, xb.x, a0); a1 = fmaf(wb.y, xb.y, a1);
        a2 = fmaf(wb.z, xb.z, a2); a3 = fmaf(wb.w, xb.w, a3);
        float a = (a0 + a1) + (a2 + a3);
        #pragma unroll
        for (int d = 16; d > 0; d >>= 1)
            a += __shfl_xor_sync(0xffffffffu, a, d);
        if (lane == 0) {
            int o = r * 16 + i;               // [0,128): 0..63 loc, 64..127 scale
            int u = (o < 64) ? (k * 64 + o) : (448 + k * 64 + (o - 64));
            g_scratch[u] = a + pb[i];
        }
    }
}

// publish flag[k] once all 8 LSTM CTAs stored their slice of row k
__device__ __forceinline__ void publish_row(int k, int t)
{
    __syncthreads();                          // row-k stores visible CTA-wide
    if (t == 0) {
        __threadfence();
        unsigned old = atomicAdd(&g_cnt[k * 8], 1u);
        if ((old & 7u) == 7u) {               // 8th CTA this replay
            __threadfence();
            st_rel(&g_flag[k * 8], 1);
        }
    }
}

// ---------------------------------------------------------------------------
// broadcast one 512KB item: (tensor,k,sub) -> 32768 float4
// ---------------------------------------------------------------------------
__device__ __forceinline__ void do_item(int j, float4* __restrict__ out, int t)
{
    const int k      = j >> 5;
    const int r2     = j & 31;
    const int tensor = r2 >> 4;
    const int sub    = r2 & 15;
    const int seg    = tensor * KSTEP + k;

    if (t == 0)
        while (!ld_acq(&g_flag[k * 8])) __nanosleep(128);
    __syncthreads();

    const float4 v = ((const float4*)g_scratch)[seg * 16 + (t & 15)];
    float4* base = out + (size_t)seg * 524288 + sub * 32768 + t;
    #pragma unroll
    for (int i = 0; i < 128; i++)
        base[i * 256] = v;
}

// ---------------------------------------------------------------------------
// Fused kernel: cluster 0 (CTAs 0..7) = LSTM + projections + flags;
// CTAs 8..143 = flag-gated broadcast.
// ---------------------------------------------------------------------------
__global__ void __cluster_dims__(CL, 1, 1) __launch_bounds__(TPB, 1)
fused_prior_kernel(const float* __restrict__ zm1,
                   const float* __restrict__ W_ih,  const float* __restrict__ W_hh,
                   const float* __restrict__ b_ih,  const float* __restrict__ b_hh,
                   const float* __restrict__ W_loc, const float* __restrict__ b_loc,
                   const float* __restrict__ W_scale, const float* __restrict__ b_scale,
                   float4* __restrict__ out)
{
    extern __shared__ __align__(16) float sm[];
    const int t   = threadIdx.x;
    const int bid = blockIdx.x;

    if (bid >= CL) {
        // ---------------- broadcast path ----------------
        const int b = bid - CL;                  // [0,136)
        do_item(b, out, t);
        if (b < NITEM - NBC)                     // b < 88: second item, k>=4
            do_item(b + NBC, out, t);
        return;
    }

    // ---------------- LSTM path ----------------
    float4* wst4  = (float4*)sm;                 // [128][65] pitched
    float*  zm_sh = sm + ZM_OFF;
    float*  h_sh  = sm + H_OFF;
    float*  gbuf_ = sm + GB_OFF;
    float*  pz    = sm + PZ_OFF;
    float*  pw    = sm + PW_OFF;                 // [16][260] pitched proj rows
    float*  pb    = sm + PB_OFF;

    const int r    = bid;                        // cluster rank
    const int half = t & 1;
    const int ol   = t >> 1;
    const int o    = r * 128 + ol;               // gate index [0,1024)

    {   // stage zm_1 (= p_z row 0)
        float z = zm1[t];
        zm_sh[t] = z;
        pz[t]    = z;
    }
    {   // prefetch this CTA's 16 projection rows into SMEM (coalesced)
        float4* pw4 = (float4*)pw;
        #pragma unroll
        for (int q = 0; q < 4; q++) {
            int idx = q * 256 + t;               // [0,1024)
            int row = idx >> 6;                  // [0,16)
            int c4  = idx & 63;
            int oo  = r * 16 + row;
            const float4* src = (const float4*)((oo < 64) ? W_loc + oo * HID
                                                          : W_scale + (oo - 64) * HID);
            pw4[row * 65 + c4] = src[c4];
        }
        if (t < 16) {
            int oo = r * 16 + t;
            pb[t] = (oo < 64) ? b_loc[oo] : b_scale[oo - 64];
        }
    }
    __syncthreads();

    // row 0 projection published ASAP so broadcast starts immediately
    proj_row(0, r, t, pw, pb, pz);
    publish_row(0, t);

    const float b_reg = b_ih[o] + b_hh[o];

    // ---- Pass A: coalesced stage of W_ih slice; fused step-1 dot (h=0) ----
    {
        const float4* Wi = (const float4*)W_ih + (size_t)r * 128 * 64;
        #pragma unroll
        for (int k = 0; k < 32; k++) {
            int idx = t + k * 256;
            wst4[(idx >> 6) * 65 + (idx & 63)] = Wi[idx];
        }
    }
    __syncthreads();

    float4 wsum[32];
    float gate1;
    {
        const float4* myrow = wst4 + ol * 65 + half * 32;
        const float4* zm4   = (const float4*)zm_sh;
        float a0 = 0.f, a1 = 0.f, a2 = 0.f, a3 = 0.f;
        #pragma unroll
        for (int i = 0; i < 32; i++) {
            float4 w = myrow[i];
            float4 z = zm4[half * 32 + i];
            wsum[i] = w;
            a0 = fmaf(w.x, z.x, a0); a1 = fmaf(w.y, z.y, a1);
            a2 = fmaf(w.z, z.z, a2); a3 = fmaf(w.w, z.w, a3);
        }
        float s = (a0 + a1) + (a2 + a3);
        s += __shfl_xor_sync(0xffffffffu, s, 1);
        gate1 = s + b_reg;
    }
    __syncthreads();

    // ---- Pass B: stage W_hh slice, accumulate into register wsum ----
    {
        const float4* Wh = (const float4*)W_hh + (size_t)r * 128 * 64;
        #pragma unroll
        for (int k = 0; k < 32; k++) {
            int idx = t + k * 256;
            wst4[(idx >> 6) * 65 + (idx & 63)] = Wh[idx];
        }
    }
    __syncthreads();
    {
        const float4* myrow = wst4 + ol * 65 + half * 32;
        #pragma unroll
        for (int i = 0; i < 32; i++) {
            float4 w = myrow[i];
            wsum[i].x += w.x; wsum[i].y += w.y;
            wsum[i].z += w.z; wsum[i].w += w.w;
        }
    }

    // ---- 6 LSTM steps, projecting + publishing each row as it appears ----
    float c_reg = 0.f;                           // thread t owns c[t]
    for (int s = 1; s <= KSTEP - 1; s++) {
        float gate;
        if (s == 1) {
            gate = gate1;
        } else {
            const float4* h4 = (const float4*)h_sh;
            float a0 = 0.f, a1 = 0.f, a2 = 0.f, a3 = 0.f;
            #pragma unroll
            for (int i = 0; i < 32; i++) {
                float4 w = wsum[i];
                float4 h = h4[half * 32 + i];
                a0 = fmaf(w.x, h.x, a0); a1 = fmaf(w.y, h.y, a1);
                a2 = fmaf(w.z, h.z, a2); a3 = fmaf(w.w, h.w, a3);
            }
            float ss = (a0 + a1) + (a2 + a3);
            ss += __shfl_xor_sync(0xffffffffu, ss, 1);
            gate = ss + b_reg;
        }

        // exchange this CTA's 128 gates to all 8 CTAs (double-buffered)
        float* gb = gbuf_ + (s & 1) * 1024;
        if (half == 0) {
            uint32_t laddr = smem_u32(&gb[o]);
            #pragma unroll
            for (int d = 0; d < CL; d++)
                st_cluster_f32(laddr, d, gate);
        }
        cluster_sync_();

        // replicated h/c update
        const int j = t;
        float gi = gb[j];
        float gf = gb[HID + j];
        float gg = gb[2 * HID + j];
        float go = gb[3 * HID + j];
        c_reg = sigf(gf) * c_reg + sigf(gi) * tanhf(gg);
        float h = sigf(go) * tanhf(c_reg);
        h_sh[j] = h;
        pz[s * HID + j] = h;
        __syncthreads();

        proj_row(s, r, t, pw, pb, pz);
        publish_row(s, t);
    }
}

extern "C" void kernel_launch(void* const* d_in, const int* in_sizes, int n_in,
                              void* d_out, int out_size)
{
    const float* zm1     = (const float*)d_in[0];
    const float* W_ih    = (const float*)d_in[1];
    const float* W_hh    = (const float*)d_in[2];
    const float* b_ih    = (const float*)d_in[3];
    const float* b_hh    = (const float*)d_in[4];
    const float* W_loc   = (const float*)d_in[5];
    const float* b_loc   = (const float*)d_in[6];
    const float* W_scale = (const float*)d_in[7];
    const float* b_scale = (const float*)d_in[8];

    static bool attr_set = false;
    if (!attr_set) {
        cudaFuncSetAttribute(fused_prior_kernel,
                             cudaFuncAttributeMaxDynamicSharedMemorySize, SMEM_BYTES);
        attr_set = true;
    }

    fused_prior_kernel<<<GRID, TPB, SMEM_BYTES>>>(zm1, W_ih, W_hh, b_ih, b_hh,
                                                  W_loc, b_loc, W_scale, b_scale,
                                                  (float4*)d_out);
}